// round 3
// baseline (speedup 1.0000x reference)
#include <cuda_runtime.h>

// ---------------------------------------------------------------------------
// GCN_11682311045288: 2-layer GCN via per-launch CSR build + gather aggregation.
//   deg (real edges) -> dinv = rsqrt(deg+1)   (+1 = self loop)
//   CSR: rowptr by dst, entries packed {src:int, norm:float}
//   L1: xw1 = x @ W1 ; h[r] = sum_in w*xw1[s] + dinv[r]^2*xw1[r] + b1
//   L2: xw2 = relu(h) @ W2 ; z likewise
// Inputs: x [N,128] f32, edge_index [2,E] int32 (JAX x64-disabled downcast),
//         W1[128,64], b1[64], W2[64,64], b2[64]
// Output: z [N,64] f32
// ---------------------------------------------------------------------------

#define MAXN 131072
#define MAXE 2097152
#define F 64
#define F2 (F / 2)   // float2 groups per row

// Scratch (module-load allocated; allowed).
__device__ float2 g_xw[(size_t)MAXN * F2];   // current layer's XW
__device__ float2 g_h [(size_t)MAXN * F2];   // layer-1 result / layer-2 input
__device__ float  g_dinv[MAXN];
__device__ int    g_deg [MAXN];              // real in-degree (no self loop)
__device__ int    g_cnt [MAXN];              // fill cursors
__device__ int    g_rowptr[MAXN];            // exclusive prefix of g_deg
__device__ int2   g_csr[MAXE];               // {src, __float_as_int(norm)}

// ---------------------------------------------------------------------------
__global__ void k_init(int n) {
    int i = blockIdx.x * blockDim.x + threadIdx.x;
    if (i < n) { g_deg[i] = 0; g_cnt[i] = 0; }
}

__global__ void k_deg_count(const int* __restrict__ dst, int E) {
    int i = blockIdx.x * blockDim.x + threadIdx.x;
    int stride = gridDim.x * blockDim.x;
    for (; i < E; i += stride)
        atomicAdd(&g_deg[dst[i]], 1);
}

// Single-block exclusive scan of g_deg -> g_rowptr, plus dinv = rsqrt(deg+1).
__global__ void k_scan_dinv(int n) {
    __shared__ int ssum[1024];
    int t = threadIdx.x;
    int chunk = (n + 1023) / 1024;
    int lo = t * chunk;
    int hi = min(lo + chunk, n);

    int mysum = 0;
    for (int i = lo; i < hi; ++i) mysum += g_deg[i];
    ssum[t] = mysum;
    __syncthreads();
    // Hillis-Steele inclusive scan over 1024 partials
    for (int off = 1; off < 1024; off <<= 1) {
        int v = (t >= off) ? ssum[t - off] : 0;
        __syncthreads();
        ssum[t] += v;
        __syncthreads();
    }
    int running = ssum[t] - mysum;   // exclusive base for this chunk
    for (int i = lo; i < hi; ++i) {
        int d = g_deg[i];
        g_rowptr[i] = running;
        running += d;
        g_dinv[i] = rsqrtf((float)(d + 1));
    }
}

__global__ void k_fill(const int* __restrict__ src,
                       const int* __restrict__ dst, int E) {
    int i = blockIdx.x * blockDim.x + threadIdx.x;
    int stride = gridDim.x * blockDim.x;
    for (; i < E; i += stride) {
        int s = src[i];
        int d = dst[i];
        int pos = g_rowptr[d] + atomicAdd(&g_cnt[d], 1);
        float w = g_dinv[s] * g_dinv[d];
        g_csr[pos] = make_int2(s, __float_as_int(w));
    }
}

// ---------------------------------------------------------------------------
// Fused GEMM: g_xw[r,f] = sum_k Xrow[r,k] * W[k,f]
// READ_GH: input rows come from g_h (with optional RELU); else from Xp.
template<int K, bool RELU, bool READ_GH>
__global__ void k_gemm(const float* __restrict__ Xp,
                       const float* __restrict__ W,
                       int n)
{
    __shared__ float Ws[K * F];
    __shared__ float xs[4][K];

    const float* __restrict__ X = READ_GH ? (const float*)g_h : Xp;
    float* __restrict__ xw = (float*)g_xw;

    int f   = threadIdx.x;          // 0..63
    int yy  = threadIdx.y;          // 0..3
    int tid = yy * 64 + f;

    for (int i = tid; i < K * F; i += 256) Ws[i] = W[i];
    __syncthreads();

    int row0 = blockIdx.x * 64;
    #pragma unroll 1
    for (int t = 0; t < 16; ++t) {
        int r = row0 + t * 4 + yy;
        if (r < n) {
            #pragma unroll
            for (int i = f; i < K; i += 64) {
                float v = X[(size_t)r * K + i];
                xs[yy][i] = RELU ? fmaxf(v, 0.0f) : v;
            }
        }
        __syncthreads();
        if (r < n) {
            float acc = 0.0f;
            #pragma unroll
            for (int k = 0; k < K; ++k)
                acc = fmaf(xs[yy][k], Ws[k * F + f], acc);
            xw[(size_t)r * F + f] = acc;
        }
        __syncthreads();
    }
}

// ---------------------------------------------------------------------------
// Gather aggregation: one warp per node. Lane l owns float2 slot l of the
// 64-float row. out[r] = sum_{e in CSR row r} w_e * xw[src_e] + dinv[r]^2*xw[r] + b
template<bool TO_GH>
__global__ void k_aggr(const float* __restrict__ b,
                       float2* __restrict__ outp, int n)
{
    float2* __restrict__ o = TO_GH ? g_h : outp;
    const float2* __restrict__ xw = g_xw;

    int warp = (blockIdx.x * blockDim.x + threadIdx.x) >> 5;
    int lane = threadIdx.x & 31;
    if (warp >= n) return;
    int r = warp;

    int beg = g_rowptr[r];
    int end = beg + g_deg[r];

    float2 acc = make_float2(0.0f, 0.0f);
    int e = beg;
    // unroll by 2 to expose MLP on the dependent csr->xw chain
    for (; e + 2 <= end; e += 2) {
        int2 sw0 = g_csr[e];
        int2 sw1 = g_csr[e + 1];
        float2 v0 = xw[(size_t)sw0.x * F2 + lane];
        float2 v1 = xw[(size_t)sw1.x * F2 + lane];
        float w0 = __int_as_float(sw0.y);
        float w1 = __int_as_float(sw1.y);
        acc.x = fmaf(w0, v0.x, acc.x);
        acc.y = fmaf(w0, v0.y, acc.y);
        acc.x = fmaf(w1, v1.x, acc.x);
        acc.y = fmaf(w1, v1.y, acc.y);
    }
    for (; e < end; ++e) {
        int2 sw = g_csr[e];
        float w = __int_as_float(sw.y);
        float2 v = xw[(size_t)sw.x * F2 + lane];
        acc.x = fmaf(w, v.x, acc.x);
        acc.y = fmaf(w, v.y, acc.y);
    }
    float di = g_dinv[r];
    float sw2 = di * di;
    float2 self = xw[(size_t)r * F2 + lane];
    acc.x = fmaf(sw2, self.x, acc.x) + b[2 * lane];
    acc.y = fmaf(sw2, self.y, acc.y) + b[2 * lane + 1];
    o[(size_t)r * F2 + lane] = acc;
}

// ---------------------------------------------------------------------------
extern "C" void kernel_launch(void* const* d_in, const int* in_sizes, int n_in,
                              void* d_out, int out_size)
{
    const float* x  = (const float*)d_in[0];
    const int*   ei = (const int*)d_in[1];
    const float* W1 = (const float*)d_in[2];
    const float* b1 = (const float*)d_in[3];
    const float* W2 = (const float*)d_in[4];
    const float* b2 = (const float*)d_in[5];
    float* out = (float*)d_out;

    const int IN = 128;
    int N = in_sizes[0] / IN;
    int E = in_sizes[1] / 2;
    const int* src = ei;
    const int* dst = ei + E;

    int nb256 = (N + 255) / 256;
    int gemm_blocks = (N + 63) / 64;
    dim3 gemm_tb(64, 4);
    int edge_blocks = 2960;                  // 148 SMs * 20, grid-stride
    int aggr_blocks = (N + 7) / 8;           // 8 warps/block, 1 warp/node

    // --- graph preprocessing (per launch) ---
    k_init<<<nb256, 256>>>(N);
    k_deg_count<<<edge_blocks, 256>>>(dst, E);
    k_scan_dinv<<<1, 1024>>>(N);
    k_fill<<<edge_blocks, 256>>>(src, dst, E);

    // --- layer 1 ---
    k_gemm<128, false, false><<<gemm_blocks, gemm_tb>>>(x, W1, N);
    k_aggr<true><<<aggr_blocks, 256>>>(b1, nullptr, N);

    // --- layer 2 ---
    k_gemm<64, true, true><<<gemm_blocks, gemm_tb>>>(nullptr, W2, N);
    k_aggr<false><<<aggr_blocks, 256>>>(b2, (float2*)out, N);
}

// round 4
// speedup vs baseline: 2.0138x; 2.0138x over previous
#include <cuda_runtime.h>

// ---------------------------------------------------------------------------
// GCN_11682311045288: 2-layer GCN via per-launch CSR build + gather aggregation.
// Inputs: x [N,128] f32, edge_index [2,E] int32, W1[128,64], b1[64], W2[64,64], b2[64]
// Output: z [N,64] f32
// ---------------------------------------------------------------------------

#define MAXN 131072
#define MAXE 2097152
#define F 64
#define F2 (F / 2)

// Scratch (module-load allocated; allowed).
__device__ float2 g_xw[(size_t)MAXN * F2];
__device__ float2 g_h [(size_t)MAXN * F2];
__device__ float  g_dinv[MAXN];
__device__ int    g_deg [MAXN];
__device__ int    g_cnt [MAXN];
__device__ int    g_rowptr[MAXN];
__device__ int    g_part[512];
__device__ int2   g_csr[MAXE];

// ---------------------------------------------------------------------------
__global__ void k_init(int n) {
    int i = blockIdx.x * blockDim.x + threadIdx.x;
    if (i < n) { g_deg[i] = 0; g_cnt[i] = 0; }
}

__global__ void k_deg_count(const int* __restrict__ dst, int E) {
    int i = blockIdx.x * blockDim.x + threadIdx.x;
    int stride = gridDim.x * blockDim.x;
    for (; i < E; i += stride)
        atomicAdd(&g_deg[dst[i]], 1);
}

// --- 3-phase exclusive scan of g_deg -> g_rowptr ---------------------------
__global__ void k_scan_part(int n) {        // grid = ceil(n/256), block 256
    __shared__ int s[256];
    int t = threadIdx.x;
    int i = blockIdx.x * 256 + t;
    int v = (i < n) ? g_deg[i] : 0;
    s[t] = v;
    __syncthreads();
    #pragma unroll
    for (int off = 1; off < 256; off <<= 1) {
        int u = (t >= off) ? s[t - off] : 0;
        __syncthreads();
        s[t] += u;
        __syncthreads();
    }
    if (i < n) g_rowptr[i] = s[t] - v;       // exclusive within block
    if (t == 255) g_part[blockIdx.x] = s[255];
}

__global__ void k_scan_mid(int nb) {        // 1 block, 512 threads (nb <= 512)
    __shared__ int s[512];
    int t = threadIdx.x;
    int v = (t < nb) ? g_part[t] : 0;
    s[t] = v;
    __syncthreads();
    #pragma unroll
    for (int off = 1; off < 512; off <<= 1) {
        int u = (t >= off) ? s[t - off] : 0;
        __syncthreads();
        s[t] += u;
        __syncthreads();
    }
    if (t < nb) g_part[t] = s[t] - v;        // exclusive block bases
}

__global__ void k_scan_apply(int n) {
    int i = blockIdx.x * 256 + threadIdx.x;
    if (i < n) {
        g_rowptr[i] += g_part[blockIdx.x];
        g_dinv[i] = rsqrtf((float)(g_deg[i] + 1));
    }
}

__global__ void k_fill(const int* __restrict__ src,
                       const int* __restrict__ dst, int E) {
    int i = blockIdx.x * blockDim.x + threadIdx.x;
    int stride = gridDim.x * blockDim.x;
    for (; i < E; i += stride) {
        int s = src[i];
        int d = dst[i];
        int pos = g_rowptr[d] + atomicAdd(&g_cnt[d], 1);
        float w = g_dinv[s] * g_dinv[d];
        g_csr[pos] = make_int2(s, __float_as_int(w));
    }
}

// ---------------------------------------------------------------------------
// Register-tiled GEMM: C[64 rows x 64 cols] per block, 256 threads,
// 16 outputs per thread (16 rows x 1 col). X tile stored transposed in smem
// (pad 68) so the 16 rows read as 4 broadcast float4 LDS per k.
template<int K, bool RELU, bool READ_GH>
__global__ void k_gemm(const float* __restrict__ Xp,
                       const float* __restrict__ W,
                       int n)
{
    __shared__ float Ws[K * 64];
    __shared__ float xst[K * 68];            // xst[k*68 + r], r in [0,64)

    const float* __restrict__ X = READ_GH ? (const float*)g_h : Xp;
    float* __restrict__ xw = (float*)g_xw;

    int tid = threadIdx.x;                   // 0..255
    int f = tid & 63;
    int g = tid >> 6;                        // 0..3
    int row0 = blockIdx.x * 64;

    // load W (K*64 floats) as float4
    {
        const float4* W4 = (const float4*)W;
        #pragma unroll
        for (int i = tid; i < K * 16; i += 256)
            ((float4*)Ws)[i] = W4[i];
    }

    // fill xst transposed: 64 rows x K cols, float4 global loads
    {
        const int KQ = K / 4;
        #pragma unroll
        for (int i = tid; i < 64 * KQ; i += 256) {
            int r = i / KQ;
            int k4 = (i - r * KQ) * 4;
            int rr = row0 + r;
            float4 v = make_float4(0.f, 0.f, 0.f, 0.f);
            if (rr < n)
                v = ((const float4*)X)[((size_t)rr * K + k4) >> 2];
            if (RELU) {
                v.x = fmaxf(v.x, 0.f); v.y = fmaxf(v.y, 0.f);
                v.z = fmaxf(v.z, 0.f); v.w = fmaxf(v.w, 0.f);
            }
            xst[(k4 + 0) * 68 + r] = v.x;
            xst[(k4 + 1) * 68 + r] = v.y;
            xst[(k4 + 2) * 68 + r] = v.z;
            xst[(k4 + 3) * 68 + r] = v.w;
        }
    }
    __syncthreads();

    float acc[16];
    #pragma unroll
    for (int i = 0; i < 16; ++i) acc[i] = 0.f;
    const int rbase = g * 16;

    #pragma unroll 4
    for (int k = 0; k < K; ++k) {
        float wv = Ws[k * 64 + f];
        const float4* xr = (const float4*)&xst[k * 68 + rbase];
        float4 a = xr[0], b = xr[1], c = xr[2], d = xr[3];
        acc[0]  = fmaf(a.x, wv, acc[0]);
        acc[1]  = fmaf(a.y, wv, acc[1]);
        acc[2]  = fmaf(a.z, wv, acc[2]);
        acc[3]  = fmaf(a.w, wv, acc[3]);
        acc[4]  = fmaf(b.x, wv, acc[4]);
        acc[5]  = fmaf(b.y, wv, acc[5]);
        acc[6]  = fmaf(b.z, wv, acc[6]);
        acc[7]  = fmaf(b.w, wv, acc[7]);
        acc[8]  = fmaf(c.x, wv, acc[8]);
        acc[9]  = fmaf(c.y, wv, acc[9]);
        acc[10] = fmaf(c.z, wv, acc[10]);
        acc[11] = fmaf(c.w, wv, acc[11]);
        acc[12] = fmaf(d.x, wv, acc[12]);
        acc[13] = fmaf(d.y, wv, acc[13]);
        acc[14] = fmaf(d.z, wv, acc[14]);
        acc[15] = fmaf(d.w, wv, acc[15]);
    }

    #pragma unroll
    for (int i = 0; i < 16; ++i) {
        int r = row0 + rbase + i;
        if (r < n) xw[(size_t)r * 64 + f] = acc[i];
    }
}

// ---------------------------------------------------------------------------
// Gather aggregation: one warp per node, lane owns float2 slot, unroll x4.
template<bool TO_GH>
__global__ void k_aggr(const float* __restrict__ b,
                       float2* __restrict__ outp, int n)
{
    float2* __restrict__ o = TO_GH ? g_h : outp;
    const float2* __restrict__ xw = g_xw;

    int warp = (blockIdx.x * blockDim.x + threadIdx.x) >> 5;
    int lane = threadIdx.x & 31;
    if (warp >= n) return;
    int r = warp;

    int beg = g_rowptr[r];
    int end = beg + g_deg[r];

    float2 acc = make_float2(0.0f, 0.0f);
    int e = beg;
    for (; e + 4 <= end; e += 4) {
        int2 sw0 = g_csr[e];
        int2 sw1 = g_csr[e + 1];
        int2 sw2 = g_csr[e + 2];
        int2 sw3 = g_csr[e + 3];
        float2 v0 = xw[(size_t)sw0.x * F2 + lane];
        float2 v1 = xw[(size_t)sw1.x * F2 + lane];
        float2 v2 = xw[(size_t)sw2.x * F2 + lane];
        float2 v3 = xw[(size_t)sw3.x * F2 + lane];
        acc.x = fmaf(__int_as_float(sw0.y), v0.x, acc.x);
        acc.y = fmaf(__int_as_float(sw0.y), v0.y, acc.y);
        acc.x = fmaf(__int_as_float(sw1.y), v1.x, acc.x);
        acc.y = fmaf(__int_as_float(sw1.y), v1.y, acc.y);
        acc.x = fmaf(__int_as_float(sw2.y), v2.x, acc.x);
        acc.y = fmaf(__int_as_float(sw2.y), v2.y, acc.y);
        acc.x = fmaf(__int_as_float(sw3.y), v3.x, acc.x);
        acc.y = fmaf(__int_as_float(sw3.y), v3.y, acc.y);
    }
    for (; e < end; ++e) {
        int2 sw = g_csr[e];
        float w = __int_as_float(sw.y);
        float2 v = xw[(size_t)sw.x * F2 + lane];
        acc.x = fmaf(w, v.x, acc.x);
        acc.y = fmaf(w, v.y, acc.y);
    }
    float di = g_dinv[r];
    float sw2 = di * di;
    float2 self = xw[(size_t)r * F2 + lane];
    acc.x = fmaf(sw2, self.x, acc.x) + b[2 * lane];
    acc.y = fmaf(sw2, self.y, acc.y) + b[2 * lane + 1];
    o[(size_t)r * F2 + lane] = acc;
}

// ---------------------------------------------------------------------------
extern "C" void kernel_launch(void* const* d_in, const int* in_sizes, int n_in,
                              void* d_out, int out_size)
{
    const float* x  = (const float*)d_in[0];
    const int*   ei = (const int*)d_in[1];
    const float* W1 = (const float*)d_in[2];
    const float* b1 = (const float*)d_in[3];
    const float* W2 = (const float*)d_in[4];
    const float* b2 = (const float*)d_in[5];
    float* out = (float*)d_out;

    const int IN = 128;
    int N = in_sizes[0] / IN;
    int E = in_sizes[1] / 2;
    const int* src = ei;
    const int* dst = ei + E;

    int nb256 = (N + 255) / 256;
    int gemm_blocks = (N + 63) / 64;
    int edge_blocks = 2960;
    int aggr_blocks = (N + 7) / 8;

    // --- graph preprocessing ---
    k_init<<<nb256, 256>>>(N);
    k_deg_count<<<edge_blocks, 256>>>(dst, E);
    k_scan_part<<<nb256, 256>>>(N);
    k_scan_mid<<<1, 512>>>(nb256);
    k_scan_apply<<<nb256, 256>>>(N);
    k_fill<<<edge_blocks, 256>>>(src, dst, E);

    // --- layer 1 ---
    k_gemm<128, false, false><<<gemm_blocks, 256>>>(x, W1, N);
    k_aggr<true><<<aggr_blocks, 256>>>(b1, nullptr, N);

    // --- layer 2 ---
    k_gemm<64, true, true><<<gemm_blocks, 256>>>(nullptr, W2, N);
    k_aggr<false><<<aggr_blocks, 256>>>(b2, (float2*)out, N);
}

// round 5
// speedup vs baseline: 2.2266x; 1.1057x over previous
#include <cuda_runtime.h>

// ---------------------------------------------------------------------------
// GCN_11682311045288: 2-layer GCN via per-launch CSR build + gather aggregation.
// Inputs: x [N,128] f32, edge_index [2,E] int32, W1[128,64], b1[64], W2[64,64], b2[64]
// Output: z [N,64] f32
// ---------------------------------------------------------------------------

#define MAXN 131072
#define MAXE 2097152
#define F 64
#define F4 (F / 4)

// Scratch (module-load allocated; allowed).
__device__ float4 g_xw[(size_t)MAXN * F4];
__device__ float4 g_h [(size_t)MAXN * F4];
__device__ float  g_dinv[MAXN];
__device__ int    g_deg [MAXN];
__device__ int    g_rowptr[MAXN];   // after k_fill: rowptr[i] + deg[i] (end)
__device__ int    g_part[512];
__device__ int2   g_csr[MAXE];

// ---------------------------------------------------------------------------
__global__ void k_init(int n) {
    int i = blockIdx.x * blockDim.x + threadIdx.x;
    if (i < n) g_deg[i] = 0;
}

__global__ void k_deg_count(const int* __restrict__ dst, int E) {
    int i = blockIdx.x * blockDim.x + threadIdx.x;
    int stride = gridDim.x * blockDim.x;
    int E4 = E >> 2;
    const int4* dst4 = (const int4*)dst;
    for (int j = i; j < E4; j += stride) {
        int4 d = dst4[j];
        atomicAdd(&g_deg[d.x], 1);
        atomicAdd(&g_deg[d.y], 1);
        atomicAdd(&g_deg[d.z], 1);
        atomicAdd(&g_deg[d.w], 1);
    }
    for (int j = (E4 << 2) + i; j < E; j += stride)
        atomicAdd(&g_deg[dst[j]], 1);
}

// --- 3-phase exclusive scan of g_deg -> g_rowptr ---------------------------
__global__ void k_scan_part(int n) {
    __shared__ int s[256];
    int t = threadIdx.x;
    int i = blockIdx.x * 256 + t;
    int v = (i < n) ? g_deg[i] : 0;
    s[t] = v;
    __syncthreads();
    #pragma unroll
    for (int off = 1; off < 256; off <<= 1) {
        int u = (t >= off) ? s[t - off] : 0;
        __syncthreads();
        s[t] += u;
        __syncthreads();
    }
    if (i < n) g_rowptr[i] = s[t] - v;
    if (t == 255) g_part[blockIdx.x] = s[255];
}

__global__ void k_scan_mid(int nb) {
    __shared__ int s[512];
    int t = threadIdx.x;
    int v = (t < nb) ? g_part[t] : 0;
    s[t] = v;
    __syncthreads();
    #pragma unroll
    for (int off = 1; off < 512; off <<= 1) {
        int u = (t >= off) ? s[t - off] : 0;
        __syncthreads();
        s[t] += u;
        __syncthreads();
    }
    if (t < nb) g_part[t] = s[t] - v;
}

__global__ void k_scan_apply(int n) {
    int i = blockIdx.x * 256 + threadIdx.x;
    if (i < n) {
        g_rowptr[i] += g_part[blockIdx.x];
        g_dinv[i] = rsqrtf((float)(g_deg[i] + 1));
    }
}

// Bumps g_rowptr[d]; after this kernel g_rowptr[i] = row end.
__global__ void k_fill(const int* __restrict__ src,
                       const int* __restrict__ dst, int E) {
    int i = blockIdx.x * blockDim.x + threadIdx.x;
    int stride = gridDim.x * blockDim.x;
    int E4 = E >> 2;
    const int4* src4 = (const int4*)src;
    const int4* dst4 = (const int4*)dst;
    for (int j = i; j < E4; j += stride) {
        int4 s = src4[j];
        int4 d = dst4[j];
        int p0 = atomicAdd(&g_rowptr[d.x], 1);
        g_csr[p0] = make_int2(s.x, __float_as_int(g_dinv[s.x] * g_dinv[d.x]));
        int p1 = atomicAdd(&g_rowptr[d.y], 1);
        g_csr[p1] = make_int2(s.y, __float_as_int(g_dinv[s.y] * g_dinv[d.y]));
        int p2 = atomicAdd(&g_rowptr[d.z], 1);
        g_csr[p2] = make_int2(s.z, __float_as_int(g_dinv[s.z] * g_dinv[d.z]));
        int p3 = atomicAdd(&g_rowptr[d.w], 1);
        g_csr[p3] = make_int2(s.w, __float_as_int(g_dinv[s.w] * g_dinv[d.w]));
    }
    for (int j = (E4 << 2) + i; j < E; j += stride) {
        int s = src[j], d = dst[j];
        int p = atomicAdd(&g_rowptr[d], 1);
        g_csr[p] = make_int2(s, __float_as_int(g_dinv[s] * g_dinv[d]));
    }
}

// ---------------------------------------------------------------------------
// Register-tiled GEMM: C[64x64] per block, 256 threads, 16 outputs/thread.
template<int K, bool RELU, bool READ_GH>
__global__ void k_gemm(const float* __restrict__ Xp,
                       const float* __restrict__ W,
                       int n)
{
    __shared__ float Ws[K * 64];
    __shared__ float xst[K * 68];

    const float* __restrict__ X = READ_GH ? (const float*)g_h : Xp;
    float* __restrict__ xw = (float*)g_xw;

    int tid = threadIdx.x;
    int f = tid & 63;
    int g = tid >> 6;
    int row0 = blockIdx.x * 64;

    {
        const float4* W4 = (const float4*)W;
        #pragma unroll
        for (int i = tid; i < K * 16; i += 256)
            ((float4*)Ws)[i] = W4[i];
    }
    {
        const int KQ = K / 4;
        #pragma unroll
        for (int i = tid; i < 64 * KQ; i += 256) {
            int r = i / KQ;
            int k4 = (i - r * KQ) * 4;
            int rr = row0 + r;
            float4 v = make_float4(0.f, 0.f, 0.f, 0.f);
            if (rr < n)
                v = ((const float4*)X)[((size_t)rr * K + k4) >> 2];
            if (RELU) {
                v.x = fmaxf(v.x, 0.f); v.y = fmaxf(v.y, 0.f);
                v.z = fmaxf(v.z, 0.f); v.w = fmaxf(v.w, 0.f);
            }
            xst[(k4 + 0) * 68 + r] = v.x;
            xst[(k4 + 1) * 68 + r] = v.y;
            xst[(k4 + 2) * 68 + r] = v.z;
            xst[(k4 + 3) * 68 + r] = v.w;
        }
    }
    __syncthreads();

    float acc[16];
    #pragma unroll
    for (int i = 0; i < 16; ++i) acc[i] = 0.f;
    const int rbase = g * 16;

    #pragma unroll 4
    for (int k = 0; k < K; ++k) {
        float wv = Ws[k * 64 + f];
        const float4* xr = (const float4*)&xst[k * 68 + rbase];
        float4 a = xr[0], b = xr[1], c = xr[2], d = xr[3];
        acc[0]  = fmaf(a.x, wv, acc[0]);
        acc[1]  = fmaf(a.y, wv, acc[1]);
        acc[2]  = fmaf(a.z, wv, acc[2]);
        acc[3]  = fmaf(a.w, wv, acc[3]);
        acc[4]  = fmaf(b.x, wv, acc[4]);
        acc[5]  = fmaf(b.y, wv, acc[5]);
        acc[6]  = fmaf(b.z, wv, acc[6]);
        acc[7]  = fmaf(b.w, wv, acc[7]);
        acc[8]  = fmaf(c.x, wv, acc[8]);
        acc[9]  = fmaf(c.y, wv, acc[9]);
        acc[10] = fmaf(c.z, wv, acc[10]);
        acc[11] = fmaf(c.w, wv, acc[11]);
        acc[12] = fmaf(d.x, wv, acc[12]);
        acc[13] = fmaf(d.y, wv, acc[13]);
        acc[14] = fmaf(d.z, wv, acc[14]);
        acc[15] = fmaf(d.w, wv, acc[15]);
    }

    #pragma unroll
    for (int i = 0; i < 16; ++i) {
        int r = row0 + rbase + i;
        if (r < n) xw[(size_t)r * 64 + f] = acc[i];
    }
}

// ---------------------------------------------------------------------------
// Gather aggregation: half-warp (16 lanes) per node, lane owns one float4.
// rowptr holds row END after k_fill; beg = end - deg.
template<bool TO_GH>
__global__ void k_aggr(const float* __restrict__ bias,
                       float4* __restrict__ outp, int n)
{
    float4* __restrict__ o = TO_GH ? g_h : outp;
    const float4* __restrict__ xw = g_xw;

    int gtid = blockIdx.x * blockDim.x + threadIdx.x;
    int node = gtid >> 4;
    int lane = threadIdx.x & 15;
    if (node >= n) return;

    int end = g_rowptr[node];
    int deg = g_deg[node];
    int beg = end - deg;

    float4 acc = make_float4(0.f, 0.f, 0.f, 0.f);
    int e = beg;
    for (; e + 4 <= end; e += 4) {
        int2 sw0 = g_csr[e];
        int2 sw1 = g_csr[e + 1];
        int2 sw2 = g_csr[e + 2];
        int2 sw3 = g_csr[e + 3];
        float4 v0 = xw[(size_t)sw0.x * F4 + lane];
        float4 v1 = xw[(size_t)sw1.x * F4 + lane];
        float4 v2 = xw[(size_t)sw2.x * F4 + lane];
        float4 v3 = xw[(size_t)sw3.x * F4 + lane];
        float w0 = __int_as_float(sw0.y);
        float w1 = __int_as_float(sw1.y);
        float w2 = __int_as_float(sw2.y);
        float w3 = __int_as_float(sw3.y);
        acc.x = fmaf(w0, v0.x, acc.x); acc.y = fmaf(w0, v0.y, acc.y);
        acc.z = fmaf(w0, v0.z, acc.z); acc.w = fmaf(w0, v0.w, acc.w);
        acc.x = fmaf(w1, v1.x, acc.x); acc.y = fmaf(w1, v1.y, acc.y);
        acc.z = fmaf(w1, v1.z, acc.z); acc.w = fmaf(w1, v1.w, acc.w);
        acc.x = fmaf(w2, v2.x, acc.x); acc.y = fmaf(w2, v2.y, acc.y);
        acc.z = fmaf(w2, v2.z, acc.z); acc.w = fmaf(w2, v2.w, acc.w);
        acc.x = fmaf(w3, v3.x, acc.x); acc.y = fmaf(w3, v3.y, acc.y);
        acc.z = fmaf(w3, v3.z, acc.z); acc.w = fmaf(w3, v3.w, acc.w);
    }
    for (; e < end; ++e) {
        int2 sw = g_csr[e];
        float w = __int_as_float(sw.y);
        float4 v = xw[(size_t)sw.x * F4 + lane];
        acc.x = fmaf(w, v.x, acc.x); acc.y = fmaf(w, v.y, acc.y);
        acc.z = fmaf(w, v.z, acc.z); acc.w = fmaf(w, v.w, acc.w);
    }
    float di = g_dinv[node];
    float sw2 = di * di;
    float4 self = xw[(size_t)node * F4 + lane];
    float4 b4 = ((const float4*)bias)[lane];
    acc.x = fmaf(sw2, self.x, acc.x) + b4.x;
    acc.y = fmaf(sw2, self.y, acc.y) + b4.y;
    acc.z = fmaf(sw2, self.z, acc.z) + b4.z;
    acc.w = fmaf(sw2, self.w, acc.w) + b4.w;
    o[(size_t)node * F4 + lane] = acc;
}

// ---------------------------------------------------------------------------
extern "C" void kernel_launch(void* const* d_in, const int* in_sizes, int n_in,
                              void* d_out, int out_size)
{
    const float* x  = (const float*)d_in[0];
    const int*   ei = (const int*)d_in[1];
    const float* W1 = (const float*)d_in[2];
    const float* b1 = (const float*)d_in[3];
    const float* W2 = (const float*)d_in[4];
    const float* b2 = (const float*)d_in[5];
    float* out = (float*)d_out;

    const int IN = 128;
    int N = in_sizes[0] / IN;
    int E = in_sizes[1] / 2;
    const int* src = ei;
    const int* dst = ei + E;

    int nb256 = (N + 255) / 256;
    int gemm_blocks = (N + 63) / 64;
    int edge_blocks = 1184;                 // 148 SMs * 8 (4x vectorized loop)
    int aggr_blocks = (N + 15) / 16;        // 16 nodes per 256-thread block

    // --- graph preprocessing ---
    k_init<<<nb256, 256>>>(N);
    k_deg_count<<<edge_blocks, 256>>>(dst, E);
    k_scan_part<<<nb256, 256>>>(N);
    k_scan_mid<<<1, 512>>>(nb256);
    k_scan_apply<<<nb256, 256>>>(N);
    k_fill<<<edge_blocks, 256>>>(src, dst, E);

    // --- layer 1 ---
    k_gemm<128, false, false><<<gemm_blocks, 256>>>(x, W1, N);
    k_aggr<true><<<aggr_blocks, 256>>>(b1, nullptr, N);

    // --- layer 2 ---
    k_gemm<64, true, true><<<gemm_blocks, 256>>>(nullptr, W2, N);
    k_aggr<false><<<aggr_blocks, 256>>>(b2, (float4*)out, N);
}